// round 7
// baseline (speedup 1.0000x reference)
#include <cuda_runtime.h>

// out[n,m,:4] = relu( zw4[n] + xwb4[m] ),  zw4 = z@W1, xwb4 = x^T@W2 + b
// N=8192, M=128, DZ=DX=128, H=4.
// Single fused kernel: per-block recompute of xwb (x is L2-resident, cheap)
// + per-block zw for its 16 rows, then full-speed broadcast-add stream.
// One launch => pay the ~5K-cycle launch overhead once, no scratch round trip.

#define N_ROWS   8192
#define M_COLS   128
#define D_Z      128
#define D_X      128
#define NBLOCKS  512
#define NTHREADS 256
#define ROWS_PB  (N_ROWS / NBLOCKS)    // 16 rows per block

__global__ __launch_bounds__(NTHREADS)
void fused_kernel(const float* __restrict__ z,
                  const float* __restrict__ x,
                  const float* __restrict__ W,
                  const float* __restrict__ b,
                  float4* __restrict__ out4)
{
    __shared__ float4 sW[D_Z + D_X];        // 4 KB, h fastest
    __shared__ float4 sPart[8][M_COLS];     // 16 KB, per-warp xwb partials
    __shared__ float4 sXWB[M_COLS];         // 2 KB
    __shared__ float4 sZW[ROWS_PB];         // 256 B

    const int tid  = threadIdx.x;
    const int bid  = blockIdx.x;
    const int lane = tid & 31;
    const int warp = tid >> 5;

    sW[tid] = reinterpret_cast<const float4*>(W)[tid];
    __syncthreads();

    // ---- Phase Z: zw for rows [bid*16, bid*16+16); warp does 2 rows, ILP'd ----
    const int n0 = bid * ROWS_PB + warp * 2;
    {
        const float4 w0 = sW[lane * 4 + 0];
        const float4 w1 = sW[lane * 4 + 1];
        const float4 w2 = sW[lane * 4 + 2];
        const float4 w3 = sW[lane * 4 + 3];

        float4 acc[2];
        #pragma unroll
        for (int r = 0; r < 2; ++r) {
            const float4 zv = reinterpret_cast<const float4*>(
                                  z + (size_t)(n0 + r) * D_Z)[lane];   // coalesced
            float4 a;
            a.x = zv.x * w0.x; a.y = zv.x * w0.y; a.z = zv.x * w0.z; a.w = zv.x * w0.w;
            a.x = fmaf(zv.y, w1.x, a.x); a.y = fmaf(zv.y, w1.y, a.y);
            a.z = fmaf(zv.y, w1.z, a.z); a.w = fmaf(zv.y, w1.w, a.w);
            a.x = fmaf(zv.z, w2.x, a.x); a.y = fmaf(zv.z, w2.y, a.y);
            a.z = fmaf(zv.z, w2.z, a.z); a.w = fmaf(zv.z, w2.w, a.w);
            a.x = fmaf(zv.w, w3.x, a.x); a.y = fmaf(zv.w, w3.y, a.y);
            a.z = fmaf(zv.w, w3.z, a.z); a.w = fmaf(zv.w, w3.w, a.w);
            acc[r] = a;
        }
        #pragma unroll
        for (int off = 16; off; off >>= 1) {    // 8 independent chains: ILP
            #pragma unroll
            for (int r = 0; r < 2; ++r) {
                acc[r].x += __shfl_xor_sync(0xffffffffu, acc[r].x, off);
                acc[r].y += __shfl_xor_sync(0xffffffffu, acc[r].y, off);
                acc[r].z += __shfl_xor_sync(0xffffffffu, acc[r].z, off);
                acc[r].w += __shfl_xor_sync(0xffffffffu, acc[r].w, off);
            }
        }
        if (lane < 2) sZW[warp * 2 + lane] = acc[lane];
    }

    // ---- Phase X: xwb (redundant per block; x stays L2-resident).
    //      Warp w owns d in [16w,16w+16); lane covers m = 4*lane..4*lane+3. ----
    {
        const float4* x4 = reinterpret_cast<const float4*>(x);
        float4 acc[4] = {{0,0,0,0},{0,0,0,0},{0,0,0,0},{0,0,0,0}};
        const int d0 = warp * 16;
        #pragma unroll
        for (int i = 0; i < 16; ++i) {
            const int d = d0 + i;
            const float4 xv = x4[d * 32 + lane];   // x[d, 4l..4l+3], coalesced
            const float4 w  = sW[D_Z + d];         // broadcast
            acc[0].x = fmaf(xv.x, w.x, acc[0].x); acc[0].y = fmaf(xv.x, w.y, acc[0].y);
            acc[0].z = fmaf(xv.x, w.z, acc[0].z); acc[0].w = fmaf(xv.x, w.w, acc[0].w);
            acc[1].x = fmaf(xv.y, w.x, acc[1].x); acc[1].y = fmaf(xv.y, w.y, acc[1].y);
            acc[1].z = fmaf(xv.y, w.z, acc[1].z); acc[1].w = fmaf(xv.y, w.w, acc[1].w);
            acc[2].x = fmaf(xv.z, w.x, acc[2].x); acc[2].y = fmaf(xv.z, w.y, acc[2].y);
            acc[2].z = fmaf(xv.z, w.z, acc[2].z); acc[2].w = fmaf(xv.z, w.w, acc[2].w);
            acc[3].x = fmaf(xv.w, w.x, acc[3].x); acc[3].y = fmaf(xv.w, w.y, acc[3].y);
            acc[3].z = fmaf(xv.w, w.z, acc[3].z); acc[3].w = fmaf(xv.w, w.w, acc[3].w);
        }
        #pragma unroll
        for (int c = 0; c < 4; ++c) sPart[warp][lane * 4 + c] = acc[c];
    }
    __syncthreads();

    if (tid < M_COLS) {
        float4 s = *reinterpret_cast<const float4*>(b);
        #pragma unroll
        for (int w = 0; w < 8; ++w) {
            const float4 p = sPart[w][tid];
            s.x += p.x; s.y += p.y; s.z += p.z; s.w += p.w;
        }
        sXWB[tid] = s;
    }
    __syncthreads();

    // ---- Stream: 16 rows * 128 m = 2048 float4 per block, 8 per thread ----
    const size_t base = (size_t)bid * (ROWS_PB * M_COLS);
    #pragma unroll
    for (int it = 0; it < 8; ++it) {
        const int i  = it * NTHREADS + tid;   // 0..2047
        const int nl = i >> 7;                // local row: warp-uniform broadcast
        const int m  = i & 127;               // conflict-free LDS.128
        const float4 a = sZW[nl];
        const float4 c = sXWB[m];
        float4 r;
        r.x = fmaxf(a.x + c.x, 0.f);
        r.y = fmaxf(a.y + c.y, 0.f);
        r.z = fmaxf(a.z + c.z, 0.f);
        r.w = fmaxf(a.w + c.w, 0.f);
        out4[base + i] = r;                   // fully coalesced STG.128
    }
}

extern "C" void kernel_launch(void* const* d_in, const int* in_sizes, int n_in,
                              void* d_out, int out_size)
{
    const float* z = (const float*)d_in[0];   // [8192,128]
    const float* x = (const float*)d_in[1];   // [128,128]
    const float* W = (const float*)d_in[2];   // [256,4]
    const float* b = (const float*)d_in[3];   // [4]
    float4* out4   = (float4*)d_out;

    fused_kernel<<<NBLOCKS, NTHREADS>>>(z, x, W, b, out4);
}

// round 8
// speedup vs baseline: 1.5038x; 1.5038x over previous
#include <cuda_runtime.h>

// out[n,m,:4] = relu( zw4[n] + xwb4[m] ),  zw4 = z@W1, xwb4 = x^T@W2 + b
// N=8192, M=128, DZ=DX=128, H=4.
//
// Kernel A (1 block):   g_xwb[128] = x^T@W2 + b   (the ONLY cross-block value)
// Kernel B (512 blocks): zw for own 16 rows (block-local!) + broadcast-add stream.
// No g_zw scratch round trip; no redundant xwb recompute (R7's mistake).

#define N_ROWS   8192
#define M_COLS   128
#define D_Z      128
#define D_X      128
#define NBLOCKS  512
#define NTHREADS 256
#define ROWS_PB  (N_ROWS / NBLOCKS)    // 16

__device__ float4 g_xwb[M_COLS];       // 2 KB

// ---------------- Kernel A: xwb only, one block ----------------
// Warp w owns d in [16w, 16w+16); lane covers m = 4*lane .. 4*lane+3.
__global__ __launch_bounds__(NTHREADS)
void xwb_kernel(const float* __restrict__ x,
                const float* __restrict__ W,
                const float* __restrict__ b)
{
    __shared__ float4 sW2[D_X];             // W2 rows (h fastest), 2 KB
    __shared__ float4 sPart[8][M_COLS];     // per-warp partials, 16 KB

    const int tid  = threadIdx.x;
    const int lane = tid & 31;
    const int warp = tid >> 5;

    if (tid < D_X) sW2[tid] = reinterpret_cast<const float4*>(W)[D_Z + tid];
    __syncthreads();

    const float4* x4 = reinterpret_cast<const float4*>(x);
    float4 acc[4] = {{0,0,0,0},{0,0,0,0},{0,0,0,0},{0,0,0,0}};
    const int d0 = warp * 16;
    #pragma unroll
    for (int i = 0; i < 16; ++i) {
        const int d = d0 + i;
        const float4 xv = x4[d * 32 + lane];   // x[d, 4l..4l+3], coalesced
        const float4 w  = sW2[d];              // broadcast
        acc[0].x = fmaf(xv.x, w.x, acc[0].x); acc[0].y = fmaf(xv.x, w.y, acc[0].y);
        acc[0].z = fmaf(xv.x, w.z, acc[0].z); acc[0].w = fmaf(xv.x, w.w, acc[0].w);
        acc[1].x = fmaf(xv.y, w.x, acc[1].x); acc[1].y = fmaf(xv.y, w.y, acc[1].y);
        acc[1].z = fmaf(xv.y, w.z, acc[1].z); acc[1].w = fmaf(xv.y, w.w, acc[1].w);
        acc[2].x = fmaf(xv.z, w.x, acc[2].x); acc[2].y = fmaf(xv.z, w.y, acc[2].y);
        acc[2].z = fmaf(xv.z, w.z, acc[2].z); acc[2].w = fmaf(xv.z, w.w, acc[2].w);
        acc[3].x = fmaf(xv.w, w.x, acc[3].x); acc[3].y = fmaf(xv.w, w.y, acc[3].y);
        acc[3].z = fmaf(xv.w, w.z, acc[3].z); acc[3].w = fmaf(xv.w, w.w, acc[3].w);
    }
    #pragma unroll
    for (int c = 0; c < 4; ++c) sPart[warp][lane * 4 + c] = acc[c];
    __syncthreads();

    if (tid < M_COLS) {
        float4 s = *reinterpret_cast<const float4*>(b);
        #pragma unroll
        for (int w = 0; w < 8; ++w) {
            const float4 p = sPart[w][tid];
            s.x += p.x; s.y += p.y; s.z += p.z; s.w += p.w;
        }
        g_xwb[tid] = s;
    }
}

// ---------------- Kernel B: block-local zw + stream ----------------
__global__ __launch_bounds__(NTHREADS)
void zw_stream_kernel(const float* __restrict__ z,
                      const float* __restrict__ W,
                      float4* __restrict__ out4)
{
    __shared__ float4 sZW[ROWS_PB];     // 256 B
    __shared__ float4 sXWB[M_COLS];     // 2 KB

    const int tid  = threadIdx.x;
    const int bid  = blockIdx.x;
    const int lane = tid & 31;
    const int warp = tid >> 5;

    // Pull the tiny xwb table (L2-resident after kernel A) into shared.
    if (tid < M_COLS) sXWB[tid] = g_xwb[tid];

    // ---- zw for rows [bid*16, bid*16+16); each warp does 2 rows, ILP'd.
    //      W1 rows read directly (L1-hit broadcast after first warp). ----
    const int n0 = bid * ROWS_PB + warp * 2;
    {
        const float4* W4 = reinterpret_cast<const float4*>(W);
        const float4 w0 = W4[lane * 4 + 0];
        const float4 w1 = W4[lane * 4 + 1];
        const float4 w2 = W4[lane * 4 + 2];
        const float4 w3 = W4[lane * 4 + 3];

        float4 acc[2];
        #pragma unroll
        for (int r = 0; r < 2; ++r) {
            const float4 zv = reinterpret_cast<const float4*>(
                                  z + (size_t)(n0 + r) * D_Z)[lane];   // coalesced
            float4 a;
            a.x = zv.x * w0.x; a.y = zv.x * w0.y; a.z = zv.x * w0.z; a.w = zv.x * w0.w;
            a.x = fmaf(zv.y, w1.x, a.x); a.y = fmaf(zv.y, w1.y, a.y);
            a.z = fmaf(zv.y, w1.z, a.z); a.w = fmaf(zv.y, w1.w, a.w);
            a.x = fmaf(zv.z, w2.x, a.x); a.y = fmaf(zv.z, w2.y, a.y);
            a.z = fmaf(zv.z, w2.z, a.z); a.w = fmaf(zv.z, w2.w, a.w);
            a.x = fmaf(zv.w, w3.x, a.x); a.y = fmaf(zv.w, w3.y, a.y);
            a.z = fmaf(zv.w, w3.z, a.z); a.w = fmaf(zv.w, w3.w, a.w);
            acc[r] = a;
        }
        #pragma unroll
        for (int off = 16; off; off >>= 1) {    // 8 independent chains: ILP
            #pragma unroll
            for (int r = 0; r < 2; ++r) {
                acc[r].x += __shfl_xor_sync(0xffffffffu, acc[r].x, off);
                acc[r].y += __shfl_xor_sync(0xffffffffu, acc[r].y, off);
                acc[r].z += __shfl_xor_sync(0xffffffffu, acc[r].z, off);
                acc[r].w += __shfl_xor_sync(0xffffffffu, acc[r].w, off);
            }
        }
        if (lane < 2) sZW[warp * 2 + lane] = acc[lane];
    }
    __syncthreads();   // the only barrier

    // ---- Stream: 16 rows * 128 m = 2048 float4 per block, 8 per thread ----
    const size_t base = (size_t)bid * (ROWS_PB * M_COLS);
    #pragma unroll
    for (int it = 0; it < 8; ++it) {
        const int i  = it * NTHREADS + tid;   // 0..2047
        const int nl = i >> 7;                // local row: warp-uniform broadcast
        const int m  = i & 127;               // conflict-free LDS.128
        const float4 a = sZW[nl];
        const float4 c = sXWB[m];
        float4 r;
        r.x = fmaxf(a.x + c.x, 0.f);
        r.y = fmaxf(a.y + c.y, 0.f);
        r.z = fmaxf(a.z + c.z, 0.f);
        r.w = fmaxf(a.w + c.w, 0.f);
        out4[base + i] = r;                   // fully coalesced STG.128
    }
}

extern "C" void kernel_launch(void* const* d_in, const int* in_sizes, int n_in,
                              void* d_out, int out_size)
{
    const float* z = (const float*)d_in[0];   // [8192,128]
    const float* x = (const float*)d_in[1];   // [128,128]
    const float* W = (const float*)d_in[2];   // [256,4]
    const float* b = (const float*)d_in[3];   // [4]
    float4* out4   = (float4*)d_out;

    xwb_kernel<<<1, NTHREADS>>>(x, W, b);
    zw_stream_kernel<<<NBLOCKS, NTHREADS>>>(z, W, out4);
}